// round 6
// baseline (speedup 1.0000x reference)
#include <cuda_runtime.h>
#include <math.h>
#include <cstdint>

#define Bb 4
#define Tt 2048
#define Ee 1024
#define Hh 64
#define ROWS (Bb*Tt)

__device__ float g_q[ROWS*Hh];
__device__ float g_k[ROWS*Hh];
__device__ float g_v[ROWS*Hh];

// ---------------------------------------------------------------------------
// Helpers: cp.async + warp-level tf32 MMA (all plain sm_80+ PTX -> compiles
// under the harness's compute_103 target; no tcgen05).
// ---------------------------------------------------------------------------
__device__ __forceinline__ uint32_t smem_u32(const void* p) {
    uint32_t a;
    asm("{ .reg .u64 t; cvta.to.shared.u64 t, %1; cvt.u32.u64 %0, t; }" : "=r"(a) : "l"(p));
    return a;
}
#define CP_ASYNC16(dst_u32, src_ptr) \
    asm volatile("cp.async.cg.shared.global [%0], [%1], 16;" :: "r"(dst_u32), "l"(src_ptr))
#define CP_COMMIT() asm volatile("cp.async.commit_group;" ::: "memory")
#define CP_WAIT0()  asm volatile("cp.async.wait_group 0;" ::: "memory")
#define CP_WAIT1()  asm volatile("cp.async.wait_group 1;" ::: "memory")

__device__ __forceinline__ uint32_t tf32_of(float x) {
    uint32_t u;
    asm("cvt.rna.tf32.f32 %0, %1;" : "=r"(u) : "f"(x));
    return u;
}
__device__ __forceinline__ void mma_tf32(float* d, const uint32_t* a, uint32_t b0, uint32_t b1) {
    asm volatile(
        "mma.sync.aligned.m16n8k8.row.col.f32.tf32.tf32.f32 "
        "{%0,%1,%2,%3}, {%4,%5,%6,%7}, {%8,%9}, {%0,%1,%2,%3};"
        : "+f"(d[0]), "+f"(d[1]), "+f"(d[2]), "+f"(d[3])
        : "r"(a[0]), "r"(a[1]), "r"(a[2]), "r"(a[3]), "r"(b0), "r"(b1));
}

// ---------------------------------------------------------------------------
// Kernel 1: fused QKV projection via mma.sync tf32x2 (3-term split).
// C[8192 x 192] = X[8192 x 1024] * [Wq|Wk|Wv], +bias, scattered to g_q/g_k/g_v.
// grid = 128 blocks (64-row stripes), 256 thr = 8 warps (4m x 2n), warp tile
// 16 x 96. K-chunks of 64, double-buffered smem via cp.async.
// smem pitches: A 68 floats, B 200 floats (conflict-free fragment gathers).
// ---------------------------------------------------------------------------
#define KCH 64
#define NCH (Ee / KCH)            // 16
#define PA 68                     // A pitch (floats)
#define PB 200                    // B pitch (floats)
#define STG_FLOATS (64 * PA + 64 * PB)     // 17152
#define QKV_SMEM_BYTES (2 * STG_FLOATS * 4)  // 137216

extern __shared__ float qkv_sm[];

__global__ __launch_bounds__(256, 1) void qkv_mma(
    const float* __restrict__ x,
    const float* __restrict__ Wq, const float* __restrict__ bq,
    const float* __restrict__ Wk, const float* __restrict__ bk,
    const float* __restrict__ Wv, const float* __restrict__ bv)
{
    const int tid  = threadIdx.x;
    const int wid  = tid >> 5;
    const int lane = tid & 31;
    const int grp  = lane >> 2;        // 0..7
    const int t4   = lane & 3;         // 0..3
    const int wm   = wid & 3;          // warp row tile (16 rows each)
    const int wn   = wid >> 2;         // warp col half (96 cols each)
    const int row0 = blockIdx.x * 64;

    const float* __restrict__ Ws[3] = { Wq, Wk, Wv };
    const uint32_t sbase = smem_u32(qkv_sm);

    float d[12][4];
    #pragma unroll
    for (int t = 0; t < 12; ++t)
        { d[t][0] = 0.f; d[t][1] = 0.f; d[t][2] = 0.f; d[t][3] = 0.f; }

    auto issue = [&](int c, int s) {
        const int k0 = c * KCH;
        const uint32_t st = sbase + (uint32_t)(s * STG_FLOATS) * 4u;
        // A: 64 rows x 16 float4
        #pragma unroll
        for (int it = 0; it < 4; ++it) {
            int i = tid + it * 256;
            int r = i >> 4, c4 = i & 15;
            CP_ASYNC16(st + (uint32_t)(r * PA + c4 * 4) * 4u,
                       x + (size_t)(row0 + r) * Ee + k0 + c4 * 4);
        }
        // B: 3 mats x 64 k-rows x 16 float4
        #pragma unroll
        for (int it = 0; it < 12; ++it) {
            int i = tid + it * 256;
            int mat = i >> 10, rem = i & 1023;
            int k = rem >> 4, c4 = rem & 15;
            CP_ASYNC16(st + (uint32_t)(64 * PA + k * PB + mat * 64 + c4 * 4) * 4u,
                       Ws[mat] + (size_t)(k0 + k) * Hh + c4 * 4);
        }
        CP_COMMIT();
    };

    issue(0, 0);

    #pragma unroll 1
    for (int c = 0; c < NCH; ++c) {
        const int s = c & 1;
        if (c + 1 < NCH) { issue(c + 1, s ^ 1); CP_WAIT1(); }
        else             { CP_WAIT0(); }
        __syncthreads();

        const float* A = qkv_sm + s * STG_FLOATS;
        const float* B = A + 64 * PA;
        const float* ar = A + (wm * 16 + grp) * PA;

        #pragma unroll
        for (int kk = 0; kk < 8; ++kk) {
            const int kb = kk * 8;
            // A fragment (rows grp/grp+8, cols t4/t4+4) + tf32x2 split
            float av0 = ar[kb + t4];
            float av1 = ar[8 * PA + kb + t4];
            float av2 = ar[kb + t4 + 4];
            float av3 = ar[8 * PA + kb + t4 + 4];
            uint32_t ah[4], al[4];
            ah[0] = tf32_of(av0); al[0] = tf32_of(av0 - __uint_as_float(ah[0]));
            ah[1] = tf32_of(av1); al[1] = tf32_of(av1 - __uint_as_float(ah[1]));
            ah[2] = tf32_of(av2); al[2] = tf32_of(av2 - __uint_as_float(ah[2]));
            ah[3] = tf32_of(av3); al[3] = tf32_of(av3 - __uint_as_float(ah[3]));

            const float* b0p = B + (kb + t4) * PB + wn * 96 + grp;
            const float* b1p = b0p + 4 * PB;
            #pragma unroll
            for (int tn = 0; tn < 12; ++tn) {
                float bv0 = b0p[tn * 8];
                float bv1 = b1p[tn * 8];
                uint32_t bh0 = tf32_of(bv0);
                uint32_t bh1 = tf32_of(bv1);
                uint32_t bl0 = tf32_of(bv0 - __uint_as_float(bh0));
                uint32_t bl1 = tf32_of(bv1 - __uint_as_float(bh1));
                mma_tf32(d[tn], ah, bh0, bh1);   // Ah*Bh
                mma_tf32(d[tn], ah, bl0, bl1);   // Ah*Bl
                mma_tf32(d[tn], al, bh0, bh1);   // Al*Bh
            }
        }
        __syncthreads();   // compute done before stage gets overwritten
    }

    // epilogue: + bias, scatter to g_q/g_k/g_v (fp32)
    float* outs[3] = { g_q, g_k, g_v };
    const float* biases[3] = { bq, bk, bv };
    const int r_hi = row0 + wm * 16 + grp;
    #pragma unroll
    for (int tn = 0; tn < 12; ++tn) {
        int ng  = wn * 96 + tn * 8 + 2 * t4;    // global col in [0,192)
        int mat = ng >> 6, nc = ng & 63;
        float b0 = biases[mat][nc], b1 = biases[mat][nc + 1];
        float* op = outs[mat];
        float2 lo = make_float2(d[tn][0] + b0, d[tn][1] + b1);
        float2 hi = make_float2(d[tn][2] + b0, d[tn][3] + b1);
        *(float2*)(op + (size_t)r_hi * Hh + nc)       = lo;
        *(float2*)(op + (size_t)(r_hi + 8) * Hh + nc) = hi;
    }
}

// ---------------------------------------------------------------------------
// Kernel 2: causal flash attention, fp32, load-balanced (unchanged, passing).
// ---------------------------------------------------------------------------
__global__ __launch_bounds__(256) void attn_kernel(float* __restrict__ out)
{
    __shared__ float sbuf[8192];
    __shared__ float msm[256], lsm[256], lgs[32];
    float* Ks = sbuf;
    float* Vs = sbuf + 4096;
    float* accS = sbuf;

    const int tidx  = threadIdx.x;
    const int qi    = tidx & 31;
    const int slice = tidx >> 5;
    const int pair  = blockIdx.x;
    const int b     = blockIdx.y;

    const float* __restrict__ kb = g_k + ((size_t)(b * Tt)) * Hh;
    const float* __restrict__ vb = g_v + ((size_t)(b * Tt)) * Hh;

    #pragma unroll 1
    for (int half = 0; half < 2; ++half) {
        const int qt  = (half == 0) ? pair : (63 - pair);
        const int qg  = qt * 32 + qi;
        const int nkt = qt / 2 + 1;

        const float* __restrict__ qrow = g_q + ((size_t)(b * Tt + qg)) * Hh;
        float4 q4[16];
        #pragma unroll
        for (int i = 0; i < 16; ++i) q4[i] = ((const float4*)qrow)[i];

        float4 a4[16];
        #pragma unroll
        for (int i = 0; i < 16; ++i) a4[i] = make_float4(0.f, 0.f, 0.f, 0.f);
        float m = -INFINITY, l = 0.f;

        for (int t0 = 0; t0 < nkt; ++t0) {
            __syncthreads();
            const float4* ksrc = (const float4*)(kb + (size_t)t0 * 64 * Hh);
            const float4* vsrc = (const float4*)(vb + (size_t)t0 * 64 * Hh);
            #pragma unroll
            for (int i = 0; i < 4; ++i) {
                ((float4*)Ks)[tidx + i * 256] = ksrc[tidx + i * 256];
                ((float4*)Vs)[tidx + i * 256] = vsrc[tidx + i * 256];
            }
            __syncthreads();

            float sloc[8];
            float tmax = -INFINITY;
            #pragma unroll
            for (int jj = 0; jj < 8; ++jj) {
                int j = jj * 8 + slice;
                const float4* kr = (const float4*)(Ks + j * Hh);
                float sx = 0.f, sy = 0.f, sz = 0.f, sw = 0.f;
                #pragma unroll
                for (int d = 0; d < 16; ++d) {
                    float4 kv = kr[d];
                    sx = fmaf(q4[d].x, kv.x, sx);
                    sy = fmaf(q4[d].y, kv.y, sy);
                    sz = fmaf(q4[d].z, kv.z, sz);
                    sw = fmaf(q4[d].w, kv.w, sw);
                }
                float s = ((sx + sy) + (sz + sw)) * 8.0f;
                if (t0 * 64 + j > qg) s = -INFINITY;
                tmax = fmaxf(tmax, s);
                sloc[jj] = s;
            }

            float mn = fmaxf(m, tmax);
            if (mn != -INFINITY) {
                float corr = __expf(m - mn);
                m = mn;
                l *= corr;
                #pragma unroll
                for (int i = 0; i < 16; ++i) {
                    a4[i].x *= corr; a4[i].y *= corr;
                    a4[i].z *= corr; a4[i].w *= corr;
                }
                #pragma unroll
                for (int jj = 0; jj < 8; ++jj) {
                    float p = __expf(sloc[jj] - mn);
                    l += p;
                    const float4* vr = (const float4*)(Vs + (jj * 8 + slice) * Hh);
                    #pragma unroll
                    for (int d = 0; d < 16; ++d) {
                        float4 vv = vr[d];
                        a4[d].x = fmaf(p, vv.x, a4[d].x);
                        a4[d].y = fmaf(p, vv.y, a4[d].y);
                        a4[d].z = fmaf(p, vv.z, a4[d].z);
                        a4[d].w = fmaf(p, vv.w, a4[d].w);
                    }
                }
            }
        }

        __syncthreads();
        msm[slice * 32 + qi] = m;
        lsm[slice * 32 + qi] = l;
        __syncthreads();

        float mg = -INFINITY;
        #pragma unroll
        for (int s2 = 0; s2 < 8; ++s2) mg = fmaxf(mg, msm[s2 * 32 + qi]);
        float lg = 0.f;
        #pragma unroll
        for (int s2 = 0; s2 < 8; ++s2)
            lg += lsm[s2 * 32 + qi] * __expf(msm[s2 * 32 + qi] - mg);
        float w = __expf(m - mg);
        if (slice == 0) lgs[qi] = lg;

        float* arow = accS + qi * 68;
        for (int r = 0; r < 8; ++r) {
            __syncthreads();
            if (slice == r) {
                #pragma unroll
                for (int d = 0; d < 16; ++d) {
                    float4 add;
                    add.x = w * a4[d].x; add.y = w * a4[d].y;
                    add.z = w * a4[d].z; add.w = w * a4[d].w;
                    if (r == 0) {
                        ((float4*)arow)[d] = add;
                    } else {
                        float4 cur = ((float4*)arow)[d];
                        cur.x += add.x; cur.y += add.y;
                        cur.z += add.z; cur.w += add.w;
                        ((float4*)arow)[d] = cur;
                    }
                }
            }
        }
        __syncthreads();

        float* op = out + ((size_t)(b * Tt + qt * 32)) * Hh;
        #pragma unroll
        for (int i = 0; i < 8; ++i) {
            int idx = i * 256 + tidx;
            int row = idx >> 6, d = idx & 63;
            op[idx] = accS[row * 68 + d] * __fdividef(1.0f, lgs[row]);
        }
    }
}

extern "C" void kernel_launch(void* const* d_in, const int* in_sizes, int n_in,
                              void* d_out, int out_size)
{
    const float* x  = (const float*)d_in[0];
    const float* Wq = (const float*)d_in[1];
    const float* bq = (const float*)d_in[2];
    const float* Wk = (const float*)d_in[3];
    const float* bk = (const float*)d_in[4];
    const float* Wv = (const float*)d_in[5];
    const float* bv = (const float*)d_in[6];
    float* out = (float*)d_out;

    cudaFuncSetAttribute(qkv_mma, cudaFuncAttributeMaxDynamicSharedMemorySize,
                         QKV_SMEM_BYTES);

    qkv_mma<<<128, 256, QKV_SMEM_BYTES>>>(x, Wq, bq, Wk, bk, Wv, bv);
    attn_kernel<<<dim3(32, 4), 256>>>(out);
}

// round 7
// speedup vs baseline: 1.9523x; 1.9523x over previous
#include <cuda_runtime.h>
#include <math.h>
#include <cstdint>

#define Bb 4
#define Tt 2048
#define Ee 1024
#define Hh 64
#define ROWS (Bb*Tt)

__device__ float g_q[ROWS*Hh];
__device__ float g_k[ROWS*Hh];
__device__ float g_v[ROWS*Hh];

// ---------------------------------------------------------------------------
// Helpers: cp.async + warp-level tf32 MMA (plain sm_80+ PTX).
// ---------------------------------------------------------------------------
__device__ __forceinline__ uint32_t smem_u32(const void* p) {
    uint32_t a;
    asm("{ .reg .u64 t; cvta.to.shared.u64 t, %1; cvt.u32.u64 %0, t; }" : "=r"(a) : "l"(p));
    return a;
}
#define CP_ASYNC16(dst_u32, src_ptr) \
    asm volatile("cp.async.cg.shared.global [%0], [%1], 16;" :: "r"(dst_u32), "l"(src_ptr))
#define CP_COMMIT() asm volatile("cp.async.commit_group;" ::: "memory")
#define CP_WAIT0()  asm volatile("cp.async.wait_group 0;" ::: "memory")
#define CP_WAIT1()  asm volatile("cp.async.wait_group 1;" ::: "memory")

__device__ __forceinline__ uint32_t tf32_of(float x) {
    uint32_t u;
    asm("cvt.rna.tf32.f32 %0, %1;" : "=r"(u) : "f"(x));
    return u;
}
__device__ __forceinline__ void mma_tf32(float* d, const uint32_t* a, uint32_t b0, uint32_t b1) {
    asm volatile(
        "mma.sync.aligned.m16n8k8.row.col.f32.tf32.tf32.f32 "
        "{%0,%1,%2,%3}, {%4,%5,%6,%7}, {%8,%9}, {%0,%1,%2,%3};"
        : "+f"(d[0]), "+f"(d[1]), "+f"(d[2]), "+f"(d[3])
        : "r"(a[0]), "r"(a[1]), "r"(a[2]), "r"(a[3]), "r"(b0), "r"(b1));
}

// ---------------------------------------------------------------------------
// Kernel 1: fused QKV projection via mma.sync tf32x2 (unchanged from R6 pass).
// ---------------------------------------------------------------------------
#define KCH 64
#define NCH (Ee / KCH)
#define PA 68
#define PB 200
#define STG_FLOATS (64 * PA + 64 * PB)
#define QKV_SMEM_BYTES (2 * STG_FLOATS * 4)

extern __shared__ float dyn_sm[];

__global__ __launch_bounds__(256, 1) void qkv_mma(
    const float* __restrict__ x,
    const float* __restrict__ Wq, const float* __restrict__ bq,
    const float* __restrict__ Wk, const float* __restrict__ bk,
    const float* __restrict__ Wv, const float* __restrict__ bv)
{
    const int tid  = threadIdx.x;
    const int wid  = tid >> 5;
    const int lane = tid & 31;
    const int grp  = lane >> 2;
    const int t4   = lane & 3;
    const int wm   = wid & 3;
    const int wn   = wid >> 2;
    const int row0 = blockIdx.x * 64;

    const float* __restrict__ Ws[3] = { Wq, Wk, Wv };
    const uint32_t sbase = smem_u32(dyn_sm);

    float d[12][4];
    #pragma unroll
    for (int t = 0; t < 12; ++t)
        { d[t][0] = 0.f; d[t][1] = 0.f; d[t][2] = 0.f; d[t][3] = 0.f; }

    auto issue = [&](int c, int s) {
        const int k0 = c * KCH;
        const uint32_t st = sbase + (uint32_t)(s * STG_FLOATS) * 4u;
        #pragma unroll
        for (int it = 0; it < 4; ++it) {
            int i = tid + it * 256;
            int r = i >> 4, c4 = i & 15;
            CP_ASYNC16(st + (uint32_t)(r * PA + c4 * 4) * 4u,
                       x + (size_t)(row0 + r) * Ee + k0 + c4 * 4);
        }
        #pragma unroll
        for (int it = 0; it < 12; ++it) {
            int i = tid + it * 256;
            int mat = i >> 10, rem = i & 1023;
            int k = rem >> 4, c4 = rem & 15;
            CP_ASYNC16(st + (uint32_t)(64 * PA + k * PB + mat * 64 + c4 * 4) * 4u,
                       Ws[mat] + (size_t)(k0 + k) * Hh + c4 * 4);
        }
        CP_COMMIT();
    };

    issue(0, 0);

    #pragma unroll 1
    for (int c = 0; c < NCH; ++c) {
        const int s = c & 1;
        if (c + 1 < NCH) { issue(c + 1, s ^ 1); CP_WAIT1(); }
        else             { CP_WAIT0(); }
        __syncthreads();

        const float* A = dyn_sm + s * STG_FLOATS;
        const float* B = A + 64 * PA;
        const float* ar = A + (wm * 16 + grp) * PA;

        #pragma unroll
        for (int kk = 0; kk < 8; ++kk) {
            const int kb = kk * 8;
            float av0 = ar[kb + t4];
            float av1 = ar[8 * PA + kb + t4];
            float av2 = ar[kb + t4 + 4];
            float av3 = ar[8 * PA + kb + t4 + 4];
            uint32_t ah[4], al[4];
            ah[0] = tf32_of(av0); al[0] = tf32_of(av0 - __uint_as_float(ah[0]));
            ah[1] = tf32_of(av1); al[1] = tf32_of(av1 - __uint_as_float(ah[1]));
            ah[2] = tf32_of(av2); al[2] = tf32_of(av2 - __uint_as_float(ah[2]));
            ah[3] = tf32_of(av3); al[3] = tf32_of(av3 - __uint_as_float(ah[3]));

            const float* b0p = B + (kb + t4) * PB + wn * 96 + grp;
            const float* b1p = b0p + 4 * PB;
            #pragma unroll
            for (int tn = 0; tn < 12; ++tn) {
                float bv0 = b0p[tn * 8];
                float bv1 = b1p[tn * 8];
                uint32_t bh0 = tf32_of(bv0);
                uint32_t bh1 = tf32_of(bv1);
                uint32_t bl0 = tf32_of(bv0 - __uint_as_float(bh0));
                uint32_t bl1 = tf32_of(bv1 - __uint_as_float(bh1));
                mma_tf32(d[tn], ah, bh0, bh1);
                mma_tf32(d[tn], ah, bl0, bl1);
                mma_tf32(d[tn], al, bh0, bh1);
            }
        }
        __syncthreads();
    }

    float* outs[3] = { g_q, g_k, g_v };
    const float* biases[3] = { bq, bk, bv };
    const int r_hi = row0 + wm * 16 + grp;
    #pragma unroll
    for (int tn = 0; tn < 12; ++tn) {
        int ng  = wn * 96 + tn * 8 + 2 * t4;
        int mat = ng >> 6, nc = ng & 63;
        float b0 = biases[mat][nc], b1 = biases[mat][nc + 1];
        float* op = outs[mat];
        float2 lo = make_float2(d[tn][0] + b0, d[tn][1] + b1);
        float2 hi = make_float2(d[tn][2] + b0, d[tn][3] + b1);
        *(float2*)(op + (size_t)r_hi * Hh + nc)       = lo;
        *(float2*)(op + (size_t)(r_hi + 8) * Hh + nc) = hi;
    }
}

// ---------------------------------------------------------------------------
// Kernel 2: causal flash attention on mma.sync tf32x2.
// grid (32 pairs, 4 batches); block = 256 thr = 8 warps: wm=wid&1 (16 rows),
// wn=wid>>1 (16-key slice). Each warp: independent online softmax over its
// slice; O partial in C-frags (32 regs); merged across wn once per half.
// K-tiles of 64 keys double-buffered raw fp32 via cp.async; tf32 h/l split
// at fragment load (3-term mma). Scale x8 folded into Q split (exact).
// ---------------------------------------------------------------------------
#define PK 68          // K/V/Q smem pitch (floats)
#define PP 20          // P smem pitch
#define PO 67          // accO pitch
#define KVSTG (64 * PK * 2)              // Ks+Vs per stage (floats) = 8704
#define OFF_Q   (2 * KVSTG)              // 17408: Qh
#define OFF_QL  (OFF_Q + 32 * PK)        // 19584: Ql
#define OFF_P   (OFF_QL + 32 * PK)       // 21760: P (8 warps x 16 x PP)
#define OFF_MS  (OFF_P + 8 * 16 * PP)    // 24320: mstat[128]
#define OFF_LS  (OFF_MS + 128)           // 24448: lstat[128]
#define OFF_LG  (OFF_LS + 128)           // 24576: lgs[32]
#define ATTN_SMEM_FLOATS (OFF_LG + 32)   // 24608
#define ATTN_SMEM_BYTES  (ATTN_SMEM_FLOATS * 4)

__global__ __launch_bounds__(256, 1) void attn_mma(float* __restrict__ out)
{
    float* sm = dyn_sm;
    const uint32_t sbase = smem_u32(sm);
    const int tid  = threadIdx.x;
    const int wid  = tid >> 5;
    const int lane = tid & 31;
    const int grp  = lane >> 2;
    const int t4   = lane & 3;
    const int wm   = wid & 1;
    const int wn   = wid >> 1;          // 0..3
    const int pair = blockIdx.x;
    const int b    = blockIdx.y;

    const float* __restrict__ kb_g = g_k + (size_t)(b * Tt) * Hh;
    const float* __restrict__ vb_g = g_v + (size_t)(b * Tt) * Hh;

    auto issue_kv = [&](int t0, int s) {
        const uint32_t st = sbase + (uint32_t)(s * KVSTG) * 4u;
        const float* ks = kb_g + (size_t)t0 * 64 * Hh;
        const float* vs = vb_g + (size_t)t0 * 64 * Hh;
        #pragma unroll
        for (int it = 0; it < 4; ++it) {
            int i = tid + it * 256;          // 0..1023
            int r = i >> 4, c4 = i & 15;
            uint32_t doff = (uint32_t)(r * PK + c4 * 4) * 4u;
            CP_ASYNC16(st + doff, ks + r * 64 + c4 * 4);
            CP_ASYNC16(st + (uint32_t)(64 * PK * 4) + doff, vs + r * 64 + c4 * 4);
        }
        CP_COMMIT();
    };

    #pragma unroll 1
    for (int half = 0; half < 2; ++half) {
        const int qt    = (half == 0) ? pair : (63 - pair);
        const int qbase = qt * 32;
        const int nkt   = qt / 2 + 1;

        __syncthreads();   // prior half fully done (accO reads, Qsm reuse)

        // stage Q: tf32 split with x8 scale folded in (exact power-of-2)
        #pragma unroll
        for (int it = 0; it < 2; ++it) {
            int i = tid + it * 256;          // 0..511
            int r = i >> 4, c4 = i & 15;
            float4 v = *(const float4*)(g_q + (size_t)(b * Tt + qbase + r) * Hh + c4 * 4);
            float4 h, l;
            h.x = __uint_as_float(tf32_of(v.x)); l.x = 8.f * __uint_as_float(tf32_of(v.x - h.x));
            h.y = __uint_as_float(tf32_of(v.y)); l.y = 8.f * __uint_as_float(tf32_of(v.y - h.y));
            h.z = __uint_as_float(tf32_of(v.z)); l.z = 8.f * __uint_as_float(tf32_of(v.z - h.z));
            h.w = __uint_as_float(tf32_of(v.w)); l.w = 8.f * __uint_as_float(tf32_of(v.w - h.w));
            h.x *= 8.f; h.y *= 8.f; h.z *= 8.f; h.w *= 8.f;
            *(float4*)(sm + OFF_Q  + r * PK + c4 * 4) = h;
            *(float4*)(sm + OFF_QL + r * PK + c4 * 4) = l;
        }

        issue_kv(0, 0);

        float Of[8][4];
        #pragma unroll
        for (int nt = 0; nt < 8; ++nt)
            { Of[nt][0] = 0.f; Of[nt][1] = 0.f; Of[nt][2] = 0.f; Of[nt][3] = 0.f; }
        float m0 = -INFINITY, m1 = -INFINITY, l0 = 0.f, l1 = 0.f;

        const int r0 = wm * 16 + grp;        // block-local row of this thread

        #pragma unroll 1
        for (int t0 = 0; t0 < nkt; ++t0) {
            const int s = t0 & 1;
            __syncthreads();                                  // prev compute done
            if (t0 + 1 < nkt) { issue_kv(t0 + 1, s ^ 1); CP_WAIT1(); }
            else              { CP_WAIT0(); }
            __syncthreads();                                  // tile data visible

            const float* Ks = sm + s * KVSTG;
            const float* Vs = Ks + 64 * PK;

            // ---- S = Qs . K^T (3-term tf32) ----
            float sf[8];
            #pragma unroll
            for (int i = 0; i < 8; ++i) sf[i] = 0.f;

            const float* qh = sm + OFF_Q  + r0 * PK;
            const float* ql = sm + OFF_QL + r0 * PK;
            #pragma unroll
            for (int kk = 0; kk < 8; ++kk) {
                const int kbm = kk * 8;
                uint32_t ah[4], al[4];
                ah[0] = __float_as_uint(qh[kbm + t4]);
                ah[1] = __float_as_uint(qh[8 * PK + kbm + t4]);
                ah[2] = __float_as_uint(qh[kbm + t4 + 4]);
                ah[3] = __float_as_uint(qh[8 * PK + kbm + t4 + 4]);
                al[0] = __float_as_uint(ql[kbm + t4]);
                al[1] = __float_as_uint(ql[8 * PK + kbm + t4]);
                al[2] = __float_as_uint(ql[kbm + t4 + 4]);
                al[3] = __float_as_uint(ql[8 * PK + kbm + t4 + 4]);
                #pragma unroll
                for (int nt = 0; nt < 2; ++nt) {
                    const float* kr = Ks + (wn * 16 + nt * 8 + grp) * PK + kbm;
                    float v0 = kr[t4], v1 = kr[t4 + 4];
                    uint32_t bh0 = tf32_of(v0), bh1 = tf32_of(v1);
                    uint32_t bl0 = tf32_of(v0 - __uint_as_float(bh0));
                    uint32_t bl1 = tf32_of(v1 - __uint_as_float(bh1));
                    mma_tf32(sf + 4 * nt, ah, bh0, bh1);
                    mma_tf32(sf + 4 * nt, ah, bl0, bl1);
                    mma_tf32(sf + 4 * nt, al, bh0, bh1);
                }
            }

            // ---- causal mask (last tile only) ----
            if (t0 == nkt - 1) {
                const int kc = t0 * 64 + wn * 16 + 2 * t4;
                const int q0 = qbase + r0, q1 = q0 + 8;
                #pragma unroll
                for (int nt = 0; nt < 2; ++nt) {
                    int k0c = kc + nt * 8;
                    if (k0c     > q0) sf[4*nt+0] = -INFINITY;
                    if (k0c + 1 > q0) sf[4*nt+1] = -INFINITY;
                    if (k0c     > q1) sf[4*nt+2] = -INFINITY;
                    if (k0c + 1 > q1) sf[4*nt+3] = -INFINITY;
                }
            }

            // ---- online softmax (per warp-slice, per row) ----
            float rmax0 = fmaxf(fmaxf(sf[0], sf[1]), fmaxf(sf[4], sf[5]));
            float rmax1 = fmaxf(fmaxf(sf[2], sf[3]), fmaxf(sf[6], sf[7]));
            rmax0 = fmaxf(rmax0, __shfl_xor_sync(0xffffffffu, rmax0, 1));
            rmax0 = fmaxf(rmax0, __shfl_xor_sync(0xffffffffu, rmax0, 2));
            rmax1 = fmaxf(rmax1, __shfl_xor_sync(0xffffffffu, rmax1, 1));
            rmax1 = fmaxf(rmax1, __shfl_xor_sync(0xffffffffu, rmax1, 2));

            float mn0 = fmaxf(m0, rmax0), mn1 = fmaxf(m1, rmax1);
            float sm0 = (mn0 == -INFINITY) ? 0.f : mn0;
            float sm1 = (mn1 == -INFINITY) ? 0.f : mn1;
            float corr0 = __expf(m0 - sm0);     // m=-inf -> 0
            float corr1 = __expf(m1 - sm1);
            m0 = mn0; m1 = mn1;

            float p[8];
            p[0] = __expf(sf[0] - sm0); p[1] = __expf(sf[1] - sm0);
            p[4] = __expf(sf[4] - sm0); p[5] = __expf(sf[5] - sm0);
            p[2] = __expf(sf[2] - sm1); p[3] = __expf(sf[3] - sm1);
            p[6] = __expf(sf[6] - sm1); p[7] = __expf(sf[7] - sm1);

            float rs0 = (p[0] + p[1]) + (p[4] + p[5]);
            float rs1 = (p[2] + p[3]) + (p[6] + p[7]);
            rs0 += __shfl_xor_sync(0xffffffffu, rs0, 1);
            rs0 += __shfl_xor_sync(0xffffffffu, rs0, 2);
            rs1 += __shfl_xor_sync(0xffffffffu, rs1, 1);
            rs1 += __shfl_xor_sync(0xffffffffu, rs1, 2);
            l0 = l0 * corr0 + rs0;
            l1 = l1 * corr1 + rs1;

            #pragma unroll
            for (int nt = 0; nt < 8; ++nt) {
                Of[nt][0] *= corr0; Of[nt][1] *= corr0;
                Of[nt][2] *= corr1; Of[nt][3] *= corr1;
            }

            // ---- stage P (C-frag -> smem, per-warp region) ----
            float* Pw = sm + OFF_P + wid * (16 * PP);
            #pragma unroll
            for (int nt = 0; nt < 2; ++nt) {
                *(float2*)(Pw + grp * PP + nt * 8 + 2 * t4)       = make_float2(p[4*nt+0], p[4*nt+1]);
                *(float2*)(Pw + (grp + 8) * PP + nt * 8 + 2 * t4) = make_float2(p[4*nt+2], p[4*nt+3]);
            }
            __syncwarp();

            // ---- O += P . V (3-term tf32) ----
            #pragma unroll
            for (int ks = 0; ks < 2; ++ks) {
                float pa0 = Pw[grp * PP + ks * 8 + t4];
                float pa1 = Pw[(grp + 8) * PP + ks * 8 + t4];
                float pa2 = Pw[grp * PP + ks * 8 + t4 + 4];
                float pa3 = Pw[(grp + 8) * PP + ks * 8 + t4 + 4];
                uint32_t ph[4], pl[4];
                ph[0] = tf32_of(pa0); pl[0] = tf32_of(pa0 - __uint_as_float(ph[0]));
                ph[1] = tf32_of(pa1); pl[1] = tf32_of(pa1 - __uint_as_float(ph[1]));
                ph[2] = tf32_of(pa2); pl[2] = tf32_of(pa2 - __uint_as_float(ph[2]));
                ph[3] = tf32_of(pa3); pl[3] = tf32_of(pa3 - __uint_as_float(ph[3]));

                const float* vb0 = Vs + (wn * 16 + ks * 8 + t4) * PK + grp;
                #pragma unroll
                for (int nt = 0; nt < 8; ++nt) {
                    float v0 = vb0[nt * 8];
                    float v1 = vb0[4 * PK + nt * 8];
                    uint32_t bh0 = tf32_of(v0), bh1 = tf32_of(v1);
                    uint32_t bl0 = tf32_of(v0 - __uint_as_float(bh0));
                    uint32_t bl1 = tf32_of(v1 - __uint_as_float(bh1));
                    mma_tf32(Of[nt], ph, bh0, bh1);
                    mma_tf32(Of[nt], ph, bl0, bl1);
                    mma_tf32(Of[nt], pl, bh0, bh1);
                }
            }
            __syncwarp();   // P reads done before next tile's P store
        }

        // ---- merge 4 wn-slices (associative softmax merge) ----
        __syncthreads();
        if (t4 == 0) {
            sm[OFF_MS + (wm * 4 + wn) * 16 + grp]     = m0;
            sm[OFF_MS + (wm * 4 + wn) * 16 + grp + 8] = m1;
            sm[OFF_LS + (wm * 4 + wn) * 16 + grp]     = l0;
            sm[OFF_LS + (wm * 4 + wn) * 16 + grp + 8] = l1;
        }
        __syncthreads();

        float mg0 = -INFINITY, mg1 = -INFINITY;
        #pragma unroll
        for (int w = 0; w < 4; ++w) {
            mg0 = fmaxf(mg0, sm[OFF_MS + (wm * 4 + w) * 16 + grp]);
            mg1 = fmaxf(mg1, sm[OFF_MS + (wm * 4 + w) * 16 + grp + 8]);
        }
        float lg0 = 0.f, lg1 = 0.f;
        #pragma unroll
        for (int w = 0; w < 4; ++w) {
            lg0 += sm[OFF_LS + (wm * 4 + w) * 16 + grp]     * __expf(sm[OFF_MS + (wm * 4 + w) * 16 + grp]     - mg0);
            lg1 += sm[OFF_LS + (wm * 4 + w) * 16 + grp + 8] * __expf(sm[OFF_MS + (wm * 4 + w) * 16 + grp + 8] - mg1);
        }
        float w0 = __expf(m0 - mg0);   // 0 if slice never saw a valid key
        float w1 = __expf(m1 - mg1);
        if (wn == 0 && t4 == 0) {
            sm[OFF_LG + r0]     = lg0;
            sm[OFF_LG + r0 + 8] = lg1;
        }
        #pragma unroll
        for (int nt = 0; nt < 8; ++nt) {
            Of[nt][0] *= w0; Of[nt][1] *= w0;
            Of[nt][2] *= w1; Of[nt][3] *= w1;
        }

        float* accO = sm;   // aliases KV stage 0 (free now)
        #pragma unroll 1
        for (int r = 0; r < 4; ++r) {
            __syncthreads();
            if (wn == r) {
                #pragma unroll
                for (int nt = 0; nt < 8; ++nt) {
                    int a0 = r0 * PO + nt * 8 + 2 * t4;
                    int a1 = (r0 + 8) * PO + nt * 8 + 2 * t4;
                    if (r == 0) {
                        accO[a0] = Of[nt][0]; accO[a0 + 1] = Of[nt][1];
                        accO[a1] = Of[nt][2]; accO[a1 + 1] = Of[nt][3];
                    } else {
                        accO[a0] += Of[nt][0]; accO[a0 + 1] += Of[nt][1];
                        accO[a1] += Of[nt][2]; accO[a1 + 1] += Of[nt][3];
                    }
                }
            }
        }
        __syncthreads();

        float* op = out + (size_t)(b * Tt + qbase) * Hh;
        #pragma unroll
        for (int it = 0; it < 8; ++it) {
            int i = tid + it * 256;          // 0..2047
            int r = i >> 6, dd = i & 63;
            op[i] = accO[r * PO + dd] * __fdividef(1.0f, sm[OFF_LG + r]);
        }
    }
}

extern "C" void kernel_launch(void* const* d_in, const int* in_sizes, int n_in,
                              void* d_out, int out_size)
{
    const float* x  = (const float*)d_in[0];
    const float* Wq = (const float*)d_in[1];
    const float* bq = (const float*)d_in[2];
    const float* Wk = (const float*)d_in[3];
    const float* bk = (const float*)d_in[4];
    const float* Wv = (const float*)d_in[5];
    const float* bv = (const float*)d_in[6];
    float* out = (float*)d_out;

    cudaFuncSetAttribute(qkv_mma, cudaFuncAttributeMaxDynamicSharedMemorySize,
                         QKV_SMEM_BYTES);
    cudaFuncSetAttribute(attn_mma, cudaFuncAttributeMaxDynamicSharedMemorySize,
                         ATTN_SMEM_BYTES);

    qkv_mma<<<128, 256, QKV_SMEM_BYTES>>>(x, Wq, bq, Wk, bk, Wv, bv);
    attn_mma<<<dim3(32, 4), 256, ATTN_SMEM_BYTES>>>(out);
}